// round 1
// baseline (speedup 1.0000x reference)
#include <cuda_runtime.h>

#define PP 8
#define TT 128
#define HH 10
#define BPB 8
#define NT (BPB*PP)   // 64 threads per block

struct Params {
  const float* feat; const float* hist; const int* relation; const int* pfl;
  const float* emb_phase; const float* w_veh; const float* b_veh;
  const float* w_hist; const float* b_hist;
  const float* gwih; const float* gwhh; const float* gbih; const float* gbhh;
  const float* w_lane; const float* b_lane; const float* emb_const;
  const float* wf; const float* bf; const float* wc; const float* bc;
  const float* wz; const float* bz; const float* wo; const float* bo;
  float* out; int B;
};

__device__ __forceinline__ float sigf(float v) {
  return __fdividef(1.0f, 1.0f + __expf(-v));
}
__device__ __forceinline__ float tanhf_fast(float v) {
  float e = __expf(-2.0f * v);
  return __fdividef(1.0f - e, 1.0f + e);
}

// Accumulate s * row[0..29] into g[0..19] (r,z gates) and gn[0..9] (n gate).
// Row is padded to 32 floats, 16B aligned -> 8x LDS.128 broadcast.
__device__ __forceinline__ void acc30(const float* row, float s, float* g, float* gn) {
#pragma unroll
  for (int c = 0; c < 8; c++) {
    float4 w = *reinterpret_cast<const float4*>(row + 4 * c);
#pragma unroll
    for (int e = 0; e < 4; e++) {
      int i = 4 * c + e;
      float wv = (e == 0) ? w.x : ((e == 1) ? w.y : ((e == 2) ? w.z : w.w));
      if (i < 20)      g[i]      = fmaf(s, wv, g[i]);
      else if (i < 30) gn[i - 20] = fmaf(s, wv, gn[i - 20]);
    }
  }
}

__global__ __launch_bounds__(NT) void frap_kernel(Params pr) {
  __shared__ __align__(16) float wih_t[4 * 32];    // [j][i], padded rows
  __shared__ __align__(16) float whh_t[10 * 32];   // [k][i], padded rows
  __shared__ float bsum[20], bihn[10], bhhn[10];
  __shared__ float whist_s[12], bhist_s[4];
  __shared__ float embph_s[8], wveh_s[4], bveh_s[4];
  __shared__ __align__(16) float wlane_s[18 * 16];
  __shared__ float blane_s[16];
  __shared__ __align__(16) float wf_s[32 * 20];
  __shared__ float bf_s[20];
  __shared__ __align__(16) float wz_s[20 * 20];
  __shared__ float bz_s[20];
  __shared__ float wo_s[20];
  __shared__ float bo_s;
  __shared__ __align__(16) float y_s[56 * 20];
  __shared__ __align__(16) float press_s[BPB * PP * 16];
  __shared__ __align__(16) float v_s[BPB * PP * 20];
  __shared__ int pfl_s[PP];

  const int tid = threadIdx.x;

  // ---- Stage 0: cooperative weight load / transpose into shared ----
  for (int idx = tid; idx < 120; idx += NT) { int i = idx >> 2, j = idx & 3; wih_t[j * 32 + i] = pr.gwih[idx]; }
  for (int idx = tid; idx < 300; idx += NT) { int i = idx / 10, k = idx % 10; whh_t[k * 32 + i] = pr.gwhh[idx]; }
  if (tid < 20) bsum[tid] = pr.gbih[tid] + pr.gbhh[tid];
  if (tid < 10) { bihn[tid] = pr.gbih[20 + tid]; bhhn[tid] = pr.gbhh[20 + tid]; }
  if (tid < 12) whist_s[tid] = pr.w_hist[tid];
  if (tid < 4) bhist_s[tid] = pr.b_hist[tid];
  if (tid < 8) embph_s[tid] = pr.emb_phase[tid];
  if (tid < 4) { wveh_s[tid] = pr.w_veh[tid]; bveh_s[tid] = pr.b_veh[tid]; }
  for (int idx = tid; idx < 288; idx += NT) wlane_s[idx] = pr.w_lane[idx];
  if (tid < 16) blane_s[tid] = pr.b_lane[tid];
  for (int idx = tid; idx < 640; idx += NT) wf_s[idx] = pr.wf[idx];
  if (tid < 20) bf_s[tid] = pr.bf[tid];
  for (int idx = tid; idx < 400; idx += NT) wz_s[idx] = pr.wz[idx];
  if (tid < 20) bz_s[tid] = pr.bz[tid];
  if (tid < 20) wo_s[tid] = pr.wo[tid];
  if (tid == 0) bo_s = pr.bo[0];
  if (tid < PP) pfl_s[tid] = pr.pfl[tid];
  __syncthreads();

  // ---- Stage 1: batch-independent y = relu(emb_const[relation] @ wc + bc) ----
  for (int idx = tid; idx < 56 * 20; idx += NT) {
    int q = idx / 20, m = idx % 20;
    int i = q / 7, jp = q % 7;
    int rel = pr.relation[i * 7 + jp];
    const float* e = pr.emb_const + rel * 4;
    float s = pr.bc[m];
#pragma unroll
    for (int c = 0; c < 4; c++) s = fmaf(e[c], pr.wc[c * 20 + m], s);
    y_s[idx] = fmaxf(s, 0.f);
  }

  const int bl = tid >> 3, p = tid & 7;
  const long b = (long)blockIdx.x * BPB + bl;
  const bool active = (b < (long)pr.B);
  const long bcl = active ? b : (long)(pr.B - 1);
  const float* hb = pr.hist + bcl * (TT * 3 * PP) + p;

  // ---- Stage 2: GRU over T=128 steps, one thread per (batch, lane) ----
  float h[HH];
#pragma unroll
  for (int i = 0; i < HH; i++) h[i] = 0.f;

  float q0 = hb[0], q1 = hb[8], q2 = hb[16];
  for (int t = 0; t < TT; t++) {
    float n0 = 0.f, n1 = 0.f, n2 = 0.f;
    if (t + 1 < TT) {                 // software prefetch next step
      const float* hn2 = hb + (t + 1) * 24;
      n0 = hn2[0]; n1 = hn2[8]; n2 = hn2[16];
    }
    // h_emb = sigmoid(hist @ w_hist + b_hist)
    float x0 = sigf(fmaf(q0, whist_s[0], fmaf(q1, whist_s[4], fmaf(q2, whist_s[8],  bhist_s[0]))));
    float x1 = sigf(fmaf(q0, whist_s[1], fmaf(q1, whist_s[5], fmaf(q2, whist_s[9],  bhist_s[1]))));
    float x2 = sigf(fmaf(q0, whist_s[2], fmaf(q1, whist_s[6], fmaf(q2, whist_s[10], bhist_s[2]))));
    float x3 = sigf(fmaf(q0, whist_s[3], fmaf(q1, whist_s[7], fmaf(q2, whist_s[11], bhist_s[3]))));

    float g[20], gn[10], hn_[10];
#pragma unroll
    for (int i = 0; i < 20; i++) g[i] = bsum[i];
#pragma unroll
    for (int i = 0; i < 10; i++) { gn[i] = bihn[i]; hn_[i] = bhhn[i]; }

    acc30(wih_t +  0, x0, g, gn);
    acc30(wih_t + 32, x1, g, gn);
    acc30(wih_t + 64, x2, g, gn);
    acc30(wih_t + 96, x3, g, gn);
#pragma unroll
    for (int k = 0; k < HH; k++) acc30(whh_t + k * 32, h[k], g, hn_);

#pragma unroll
    for (int i = 0; i < HH; i++) {
      float r = sigf(g[i]);
      float z = sigf(g[10 + i]);
      float n = tanhf_fast(fmaf(r, hn_[i], gn[i]));
      h[i] = fmaf(z, h[i] - n, n);     // (1-z)*n + z*h
    }
    q0 = n0; q1 = n1; q2 = n2;
  }

  // ---- Stage 3: lane projection -> pressure, and v = press @ wf[16:32] ----
  {
    float lf[18];
    float veh = pr.feat[bcl * 16 + 8 + p];
    int pidx = (int)pr.feat[bcl * 16 + p];
#pragma unroll
    for (int j = 0; j < 4; j++) lf[j] = sigf(fmaf(veh, wveh_s[j], bveh_s[j]));
#pragma unroll
    for (int j = 0; j < 4; j++) lf[4 + j] = sigf(embph_s[pidx * 4 + j]);
#pragma unroll
    for (int i = 0; i < HH; i++) lf[8 + i] = h[i];

    float lp[16];
#pragma unroll
    for (int m = 0; m < 16; m++) lp[m] = blane_s[m];
#pragma unroll
    for (int k = 0; k < 18; k++) {
      float s = lf[k];
#pragma unroll
      for (int m = 0; m < 16; m++) lp[m] = fmaf(s, wlane_s[k * 16 + m], lp[m]);
    }
#pragma unroll
    for (int m = 0; m < 16; m++) {
      lp[m] = 2.0f * fmaxf(lp[m], 0.f);      // pressure = 2*relu(...)
      press_s[tid * 16 + m] = lp[m];
    }
    float vv[20];
#pragma unroll
    for (int m = 0; m < 20; m++) vv[m] = 0.f;
#pragma unroll
    for (int k = 0; k < 16; k++) {
      float s = lp[k];
#pragma unroll
      for (int m = 0; m < 20; m++) vv[m] = fmaf(s, wf_s[(16 + k) * 20 + m], vv[m]);
    }
#pragma unroll
    for (int m = 0; m < 20; m++) v_s[tid * 20 + m] = vv[m];
  }
  __syncthreads();

  // ---- Stage 4: pair network. Thread = (batch, phase i), 7 pairs each ----
  {
    const int iph = p;
    const int li = pfl_s[iph];
    const float* pi = &press_s[(bl * 8 + li) * 16];

    float u[20];
#pragma unroll
    for (int m = 0; m < 20; m++) u[m] = bf_s[m];
#pragma unroll
    for (int k = 0; k < 16; k++) {
      float s = pi[k];
#pragma unroll
      for (int m = 0; m < 20; m++) u[m] = fmaf(s, wf_s[k * 20 + m], u[m]);
    }

    float acc = 0.f;
    for (int jp = 0; jp < 7; jp++) {
      int j = jp + (jp >= iph ? 1 : 0);
      int lj = pfl_s[j];
      const float* vj = &v_s[(bl * 8 + lj) * 20];
      const float* yq = &y_s[(iph * 7 + jp) * 20];
      float ttv[20];
#pragma unroll
      for (int m = 0; m < 20; m++) ttv[m] = fmaxf(u[m] + vj[m], 0.f) * yq[m];
      float z2[20];
#pragma unroll
      for (int m = 0; m < 20; m++) z2[m] = bz_s[m];
#pragma unroll
      for (int m = 0; m < 20; m++) {
        float s = ttv[m];
#pragma unroll
        for (int m2 = 0; m2 < 20; m2++) z2[m2] = fmaf(s, wz_s[m * 20 + m2], z2[m2]);
      }
      float zs = bo_s;
#pragma unroll
      for (int m2 = 0; m2 < 20; m2++) zs = fmaf(fmaxf(z2[m2], 0.f), wo_s[m2], zs);
      acc += zs;
    }
    if (active) pr.out[b * PP + iph] = acc;
  }
}

extern "C" void kernel_launch(void* const* d_in, const int* in_sizes, int n_in,
                              void* d_out, int out_size) {
  Params pr;
  pr.feat      = (const float*)d_in[0];
  pr.hist      = (const float*)d_in[1];
  pr.relation  = (const int*)  d_in[2];
  pr.pfl       = (const int*)  d_in[3];
  pr.emb_phase = (const float*)d_in[4];
  pr.w_veh     = (const float*)d_in[5];
  pr.b_veh     = (const float*)d_in[6];
  pr.w_hist    = (const float*)d_in[7];
  pr.b_hist    = (const float*)d_in[8];
  pr.gwih      = (const float*)d_in[9];
  pr.gwhh      = (const float*)d_in[10];
  pr.gbih      = (const float*)d_in[11];
  pr.gbhh      = (const float*)d_in[12];
  pr.w_lane    = (const float*)d_in[13];
  pr.b_lane    = (const float*)d_in[14];
  pr.emb_const = (const float*)d_in[15];
  pr.wf        = (const float*)d_in[16];
  pr.bf        = (const float*)d_in[17];
  pr.wc        = (const float*)d_in[18];
  pr.bc        = (const float*)d_in[19];
  pr.wz        = (const float*)d_in[20];
  pr.bz        = (const float*)d_in[21];
  pr.wo        = (const float*)d_in[22];
  pr.bo        = (const float*)d_in[23];
  pr.out       = (float*)d_out;
  pr.B         = in_sizes[0] / (2 * PP);

  int grid = (pr.B + BPB - 1) / BPB;
  frap_kernel<<<grid, NT>>>(pr);
}

// round 2
// speedup vs baseline: 1.4041x; 1.4041x over previous
#include <cuda_runtime.h>

#define PP 8
#define TT 128
#define HH 10
#define BPB 4
#define NT (BPB*PP*2)   // 64 threads: 4 batches x 8 lanes x 2 subs

typedef unsigned long long ull;

struct Params {
  const float* feat; const float* hist; const int* relation; const int* pfl;
  const float* emb_phase; const float* w_veh; const float* b_veh;
  const float* w_hist; const float* b_hist;
  const float* gwih; const float* gwhh; const float* gbih; const float* gbhh;
  const float* w_lane; const float* b_lane; const float* emb_const;
  const float* wf; const float* bf; const float* wc; const float* bc;
  const float* wz; const float* bz; const float* wo; const float* bo;
  float* out; int B;
};

__device__ __forceinline__ ull pk2(float v) {
  ull d; asm("mov.b64 %0, {%1, %1};" : "=l"(d) : "f"(v)); return d;
}
__device__ __forceinline__ ull f2fma(ull a, ull b, ull c) {
  ull d; asm("fma.rn.f32x2 %0, %1, %2, %3;" : "=l"(d) : "l"(a), "l"(b), "l"(c)); return d;
}
__device__ __forceinline__ void upk(ull v, float& lo, float& hi) {
  asm("mov.b64 {%0, %1}, %2;" : "=f"(lo), "=f"(hi) : "l"(v));
}
__device__ __forceinline__ float tanh_ap(float x) {
  float y; asm("tanh.approx.f32 %0, %1;" : "=f"(y) : "f"(x)); return y;
}
__device__ __forceinline__ float sigf(float v) {
  return fmaf(tanh_ap(0.5f * v), 0.5f, 0.5f);
}

__global__ __launch_bounds__(NT, 12) void frap_kernel(Params pr) {
  // GRU split weights: [k][sub][16]; k: 0..3 = x inputs, 4..13 = h inputs
  // (4..8 = own half h, 9..13 = other half h). pos: 0..4 r, 5..9 z, 10..14 n, 15 pad.
  __shared__ __align__(16) float wsp[14][2][16];
  __shared__ __align__(16) float brz_s[2][16];  // r,z bias sums (10 used)
  __shared__ __align__(16) float bn_s[2][8];    // bih_n (5 used)
  __shared__ __align__(16) float bh_s[2][8];    // bhh_n (5 used)
  __shared__ float whist_s[12], bhist_s[4];
  __shared__ float embph_s[8], wveh_s[4], bveh_s[4];
  __shared__ __align__(16) float wlane_s[18 * 16];
  __shared__ float blane_s[16];
  __shared__ __align__(16) float wf_s[32 * 20];
  __shared__ float bf_s[20];
  __shared__ __align__(16) float wz_s[20 * 20];
  __shared__ float bz_s[20];
  __shared__ float wo_s[20];
  __shared__ float bo_s;
  __shared__ float wc_s[4 * 20], bc_s[20], embc_s[8];
  __shared__ int rel_s[56];
  __shared__ __align__(16) float press_s[BPB * PP * 16];
  __shared__ __align__(16) float v_s[BPB * PP * 20];
  __shared__ int pfl_s[PP];

  const int tid = threadIdx.x;
  const int sub = tid & 1;
  const int lpair = tid >> 1;          // 0..31 : bl*8 + p
  const int bl = lpair >> 3, p = lpair & 7;

  // ---- Stage 0: weight prep ----
  for (int idx = tid; idx < 448; idx += NT) {
    int k = idx >> 5, rem = idx & 31, s = rem >> 4, pos = rem & 15;
    float v = 0.f;
    if (pos < 15) {
      int g = pos < 5 ? 0 : (pos < 10 ? 1 : 2);
      int j = pos - g * 5;
      int grow = g * 10 + 5 * s + j;
      if (k < 4) v = pr.gwih[grow * 4 + k];
      else {
        int kk = k - 4;
        int hidx = kk < 5 ? 5 * s + kk : 5 * (1 - s) + (kk - 5);
        v = pr.gwhh[grow * 10 + hidx];
      }
    }
    wsp[k][s][pos] = v;
  }
  if (tid < 32) {
    int s = tid >> 4, pos = tid & 15; float v = 0.f;
    if (pos < 5)       v = pr.gbih[5 * s + pos] + pr.gbhh[5 * s + pos];
    else if (pos < 10) v = pr.gbih[10 + 5 * s + (pos - 5)] + pr.gbhh[10 + 5 * s + (pos - 5)];
    brz_s[s][pos] = v;
  }
  if (tid < 16) {
    int s = tid >> 3, pos = tid & 7;
    bn_s[s][pos] = pos < 5 ? pr.gbih[20 + 5 * s + pos] : 0.f;
    bh_s[s][pos] = pos < 5 ? pr.gbhh[20 + 5 * s + pos] : 0.f;
  }
  if (tid < 12) whist_s[tid] = pr.w_hist[tid];
  if (tid < 4) bhist_s[tid] = pr.b_hist[tid];
  if (tid < 8) embph_s[tid] = pr.emb_phase[tid];
  if (tid < 4) { wveh_s[tid] = pr.w_veh[tid]; bveh_s[tid] = pr.b_veh[tid]; }
  for (int idx = tid; idx < 288; idx += NT) wlane_s[idx] = pr.w_lane[idx];
  if (tid < 16) blane_s[tid] = pr.b_lane[tid];
  for (int idx = tid; idx < 640; idx += NT) wf_s[idx] = pr.wf[idx];
  if (tid < 20) bf_s[tid] = pr.bf[tid];
  for (int idx = tid; idx < 400; idx += NT) wz_s[idx] = pr.wz[idx];
  if (tid < 20) bz_s[tid] = pr.bz[tid];
  if (tid < 20) wo_s[tid] = pr.wo[tid];
  if (tid == 0) bo_s = pr.bo[0];
  for (int idx = tid; idx < 80; idx += NT) wc_s[idx] = pr.wc[idx];
  if (tid < 20) bc_s[tid] = pr.bc[tid];
  if (tid < 8) embc_s[tid] = pr.emb_const[tid];
  if (tid < 56) rel_s[tid] = pr.relation[tid];
  if (tid < PP) pfl_s[tid] = pr.pfl[tid];
  __syncthreads();

  const long b = (long)blockIdx.x * BPB + bl;
  const bool active = (b < (long)pr.B);
  const long bcl = active ? b : (long)(pr.B - 1);
  const float* hb = pr.hist + bcl * (TT * 3 * PP) + p;

  // ---- Stage 1: GRU over T=128, 2 threads per (batch,lane) ----
  float h[5], ho[5];
#pragma unroll
  for (int j = 0; j < 5; j++) { h[j] = 0.f; ho[j] = 0.f; }

  const ull* bz2 = (const ull*)brz_s[sub];
  const ull* bn2 = (const ull*)bn_s[sub];
  const ull* bh2 = (const ull*)bh_s[sub];

  float q0 = hb[0], q1 = hb[8], q2 = hb[16];
  for (int t = 0; t < TT; t++) {
    float n0 = 0.f, n1 = 0.f, n2 = 0.f;
    if (t + 1 < TT) {
      const float* hn2p = hb + (t + 1) * 24;
      n0 = hn2p[0]; n1 = hn2p[8]; n2 = hn2p[16];
    }
    float x0 = sigf(fmaf(q0, whist_s[0], fmaf(q1, whist_s[4], fmaf(q2, whist_s[8],  bhist_s[0]))));
    float x1 = sigf(fmaf(q0, whist_s[1], fmaf(q1, whist_s[5], fmaf(q2, whist_s[9],  bhist_s[1]))));
    float x2 = sigf(fmaf(q0, whist_s[2], fmaf(q1, whist_s[6], fmaf(q2, whist_s[10], bhist_s[2]))));
    float x3 = sigf(fmaf(q0, whist_s[3], fmaf(q1, whist_s[7], fmaf(q2, whist_s[11], bhist_s[3]))));

    ull aRZ[5], aN[3], aH[3];
#pragma unroll
    for (int i = 0; i < 5; i++) aRZ[i] = bz2[i];
#pragma unroll
    for (int i = 0; i < 3; i++) { aN[i] = bn2[i]; aH[i] = bh2[i]; }

    float vals[14] = {x0, x1, x2, x3,
                      h[0], h[1], h[2], h[3], h[4],
                      ho[0], ho[1], ho[2], ho[3], ho[4]};
#pragma unroll
    for (int k = 0; k < 14; k++) {
      ull s2 = pk2(vals[k]);
      const ulonglong2* rw = (const ulonglong2*)&wsp[k][sub][0];
      ulonglong2 w01 = rw[0];
      ulonglong2 w23 = rw[1];
      ulonglong2 w45 = rw[2];
      ulonglong2 w67 = rw[3];
      aRZ[0] = f2fma(s2, w01.x, aRZ[0]);
      aRZ[1] = f2fma(s2, w01.y, aRZ[1]);
      aRZ[2] = f2fma(s2, w23.x, aRZ[2]);
      aRZ[3] = f2fma(s2, w23.y, aRZ[3]);
      aRZ[4] = f2fma(s2, w45.x, aRZ[4]);
      if (k < 4) {
        aN[0] = f2fma(s2, w45.y, aN[0]);
        aN[1] = f2fma(s2, w67.x, aN[1]);
        aN[2] = f2fma(s2, w67.y, aN[2]);
      } else {
        aH[0] = f2fma(s2, w45.y, aH[0]);
        aH[1] = f2fma(s2, w67.x, aH[1]);
        aH[2] = f2fma(s2, w67.y, aH[2]);
      }
    }
    float a[10], an[6], ah[6];
#pragma unroll
    for (int i = 0; i < 5; i++) upk(aRZ[i], a[2 * i], a[2 * i + 1]);
#pragma unroll
    for (int i = 0; i < 3; i++) { upk(aN[i], an[2 * i], an[2 * i + 1]); upk(aH[i], ah[2 * i], ah[2 * i + 1]); }

#pragma unroll
    for (int j = 0; j < 5; j++) {
      float r = sigf(a[j]);
      float z = sigf(a[5 + j]);
      float n = tanh_ap(fmaf(r, ah[j], an[j]));
      h[j] = fmaf(z, h[j] - n, n);
    }
#pragma unroll
    for (int j = 0; j < 5; j++) ho[j] = __shfl_xor_sync(0xffffffffu, h[j], 1);
    q0 = n0; q1 = n1; q2 = n2;
  }

  // ---- Stage 2: lane projection -> pressure, v = press @ wf[16:32] ----
  {
    float ha[10];
#pragma unroll
    for (int j = 0; j < 5; j++) {
      ha[j]     = (sub == 0) ? h[j]  : ho[j];
      ha[5 + j] = (sub == 0) ? ho[j] : h[j];
    }
    float lf[18];
    float veh = pr.feat[bcl * 16 + 8 + p];
    int pidx = (int)pr.feat[bcl * 16 + p];
#pragma unroll
    for (int j = 0; j < 4; j++) lf[j] = sigf(fmaf(veh, wveh_s[j], bveh_s[j]));
#pragma unroll
    for (int j = 0; j < 4; j++) lf[4 + j] = sigf(embph_s[pidx * 4 + j]);
#pragma unroll
    for (int i = 0; i < HH; i++) lf[8 + i] = ha[i];

    // split lp across subs: sub computes m in [8*sub, 8*sub+8)
#pragma unroll
    for (int mm = 0; mm < 8; mm++) {
      int m = 8 * sub + mm;
      float s = blane_s[m];
#pragma unroll
      for (int k = 0; k < 18; k++) s = fmaf(lf[k], wlane_s[k * 16 + m], s);
      press_s[lpair * 16 + m] = 2.0f * fmaxf(s, 0.f);
    }
    __syncwarp();
    float pf[16];
#pragma unroll
    for (int k = 0; k < 16; k++) pf[k] = press_s[lpair * 16 + k];
#pragma unroll
    for (int mm = 0; mm < 10; mm++) {
      int m = 10 * sub + mm;
      float s = 0.f;
#pragma unroll
      for (int k = 0; k < 16; k++) s = fmaf(pf[k], wf_s[(16 + k) * 20 + m], s);
      v_s[lpair * 20 + m] = s;
    }
  }
  __syncthreads();

  // ---- Stage 3: pair network; sub0 handles jp 0..3, sub1 jp 4..6 ----
  {
    const int iph = p;
    const int li = pfl_s[iph];
    const float* pi = &press_s[(bl * 8 + li) * 16];

    float u[20];
#pragma unroll
    for (int m = 0; m < 20; m++) u[m] = bf_s[m];
#pragma unroll
    for (int k = 0; k < 16; k++) {
      float s = pi[k];
#pragma unroll
      for (int m = 0; m < 20; m++) u[m] = fmaf(s, wf_s[k * 20 + m], u[m]);
    }

    float acc = 0.f;
    const int jpS = sub ? 4 : 0;
    const int jpE = sub ? 7 : 4;
    for (int jp = jpS; jp < jpE; jp++) {
      int j = jp + (jp >= iph ? 1 : 0);
      int lj = pfl_s[j];
      const float* vj = &v_s[(bl * 8 + lj) * 20];
      int rel = rel_s[iph * 7 + jp];
      const float* e = &embc_s[rel * 4];
      float ttv[20];
#pragma unroll
      for (int m = 0; m < 20; m++) {
        float y = bc_s[m];
#pragma unroll
        for (int c = 0; c < 4; c++) y = fmaf(e[c], wc_s[c * 20 + m], y);
        y = fmaxf(y, 0.f);
        ttv[m] = fmaxf(u[m] + vj[m], 0.f) * y;
      }
      float z2[20];
#pragma unroll
      for (int m = 0; m < 20; m++) z2[m] = bz_s[m];
#pragma unroll
      for (int m = 0; m < 20; m++) {
        float s = ttv[m];
#pragma unroll
        for (int m2 = 0; m2 < 20; m2++) z2[m2] = fmaf(s, wz_s[m * 20 + m2], z2[m2]);
      }
      float zs = bo_s;
#pragma unroll
      for (int m2 = 0; m2 < 20; m2++) zs = fmaf(fmaxf(z2[m2], 0.f), wo_s[m2], zs);
      acc += zs;
    }
    __syncwarp();
    acc += __shfl_xor_sync(0xffffffffu, acc, 1);
    if (sub == 0 && active) pr.out[b * PP + iph] = acc;
  }
}

extern "C" void kernel_launch(void* const* d_in, const int* in_sizes, int n_in,
                              void* d_out, int out_size) {
  Params pr;
  pr.feat      = (const float*)d_in[0];
  pr.hist      = (const float*)d_in[1];
  pr.relation  = (const int*)  d_in[2];
  pr.pfl       = (const int*)  d_in[3];
  pr.emb_phase = (const float*)d_in[4];
  pr.w_veh     = (const float*)d_in[5];
  pr.b_veh     = (const float*)d_in[6];
  pr.w_hist    = (const float*)d_in[7];
  pr.b_hist    = (const float*)d_in[8];
  pr.gwih      = (const float*)d_in[9];
  pr.gwhh      = (const float*)d_in[10];
  pr.gbih      = (const float*)d_in[11];
  pr.gbhh      = (const float*)d_in[12];
  pr.w_lane    = (const float*)d_in[13];
  pr.b_lane    = (const float*)d_in[14];
  pr.emb_const = (const float*)d_in[15];
  pr.wf        = (const float*)d_in[16];
  pr.bf        = (const float*)d_in[17];
  pr.wc        = (const float*)d_in[18];
  pr.bc        = (const float*)d_in[19];
  pr.wz        = (const float*)d_in[20];
  pr.bz        = (const float*)d_in[21];
  pr.wo        = (const float*)d_in[22];
  pr.bo        = (const float*)d_in[23];
  pr.out       = (float*)d_out;
  pr.B         = in_sizes[0] / (2 * PP);

  int grid = (pr.B + BPB - 1) / BPB;
  frap_kernel<<<grid, NT>>>(pr);
}

// round 3
// speedup vs baseline: 2.9191x; 2.0790x over previous
#include <cuda_runtime.h>

#define PP 8
#define TT 128
#define BPB 4
#define NT 128
#define MAXB 8192

typedef unsigned long long ull;

struct Params {
  const float* feat; const float* hist; const int* relation; const int* pfl;
  const float* emb_phase; const float* w_veh; const float* b_veh;
  const float* w_hist; const float* b_hist;
  const float* gwih; const float* gwhh; const float* gbih; const float* gbhh;
  const float* w_lane; const float* b_lane; const float* emb_const;
  const float* wf; const float* bf; const float* wc; const float* bc;
  const float* wz; const float* bz; const float* wo; const float* bo;
  float* out; int B;
};

// scratch (static device memory — no allocations)
__device__ __align__(16) float  g_wbuf[2][2][7][16];
__device__ __align__(16) float  g_bias[2][24];
__device__ __align__(16) float4 g_xbuf[(size_t)MAXB * TT * PP];

__device__ __forceinline__ ull pk2(float v) {
  ull d; asm("mov.b64 %0, {%1, %1};" : "=l"(d) : "f"(v)); return d;
}
__device__ __forceinline__ ull f2fma(ull a, ull b, ull c) {
  ull d; asm("fma.rn.f32x2 %0, %1, %2, %3;" : "=l"(d) : "l"(a), "l"(b), "l"(c)); return d;
}
__device__ __forceinline__ ull add2(ull a, ull b) {
  ull d; asm("add.rn.f32x2 %0, %1, %2;" : "=l"(d) : "l"(a), "l"(b)); return d;
}
__device__ __forceinline__ void upk(ull v, float& lo, float& hi) {
  asm("mov.b64 {%0, %1}, %2;" : "=f"(lo), "=f"(hi) : "l"(v));
}
__device__ __forceinline__ float tanh_ap(float x) {
  float y; asm("tanh.approx.f32 %0, %1;" : "=f"(y) : "f"(x)); return y;
}
__device__ __forceinline__ float sigf(float v) {
  return fmaf(tanh_ap(0.5f * v), 0.5f, 0.5f);
}

// ---------------- prep: rearrange GRU weights for the (s,c) split ----------------
__global__ void prep_weights(const float* __restrict__ gwih, const float* __restrict__ gwhh,
                             const float* __restrict__ gbih, const float* __restrict__ gbhh) {
  int tid = threadIdx.x;
  for (int idx = tid; idx < 2 * 2 * 7 * 16; idx += blockDim.x) {
    int pos = idx & 15;
    int kk  = (idx >> 4) % 7;
    int c   = (idx >> 4) / 7 % 2;
    int s   = (idx >> 4) / 14;
    float v = 0.f;
    if (pos < 15) {
      int g = pos / 5, j = pos % 5;
      int grow = g * 10 + 5 * s + j;     // gate rows: r 0..9, z 10..19, n 20..29
      if (c == 0) {
        if (kk < 4) v = gwih[grow * 4 + kk];
        else        v = gwhh[grow * 10 + 5 * s + (kk - 4)];
      } else {
        int hcol = (kk < 2) ? (5 * s + 3 + kk) : (5 * (1 - s) + (kk - 2));
        v = gwhh[grow * 10 + hcol];
      }
    }
    g_wbuf[s][c][kk][pos] = v;
  }
  for (int idx = tid; idx < 48; idx += blockDim.x) {
    int s = idx / 24, pos = idx % 24;
    float v = 0.f;
    if (pos < 10) { int g = pos / 5, j = pos % 5; int grow = g * 10 + 5 * s + j; v = gbih[grow] + gbhh[grow]; }
    else if (pos >= 10 && pos < 15) v = gbih[20 + 5 * s + (pos - 10)];  // aN bias (bih_n)
    else if (pos >= 16 && pos < 21) v = gbhh[20 + 5 * s + (pos - 16)];  // aH bias (bhh_n)
    g_bias[s][pos] = v;
  }
}

// ---------------- precompute x = sigmoid(hist @ w_hist + b_hist) ----------------
__global__ __launch_bounds__(256) void precomp_x(const float* __restrict__ hist,
                                                 const float* __restrict__ w_hist,
                                                 const float* __restrict__ b_hist, int B) {
  long idx = (long)blockIdx.x * blockDim.x + threadIdx.x;   // over B*T
  if (idx >= (long)B * TT) return;
  const float4* row4 = reinterpret_cast<const float4*>(hist + idx * 24);
  float q[24];
  float4 rr;
#pragma unroll
  for (int i = 0; i < 6; i++) {
    rr = row4[i];
    q[4 * i] = rr.x; q[4 * i + 1] = rr.y; q[4 * i + 2] = rr.z; q[4 * i + 3] = rr.w;
  }
  float w[12], bb[4];
#pragma unroll
  for (int i = 0; i < 12; i++) w[i] = w_hist[i];
#pragma unroll
  for (int j = 0; j < 4; j++) bb[j] = b_hist[j];
  float4* dst = &g_xbuf[idx * PP];
#pragma unroll
  for (int p = 0; p < PP; p++) {
    float q0 = q[p], q1 = q[8 + p], q2 = q[16 + p];
    float4 x;
    x.x = sigf(fmaf(q0, w[0], fmaf(q1, w[4], fmaf(q2, w[8],  bb[0]))));
    x.y = sigf(fmaf(q0, w[1], fmaf(q1, w[5], fmaf(q2, w[9],  bb[1]))));
    x.z = sigf(fmaf(q0, w[2], fmaf(q1, w[6], fmaf(q2, w[10], bb[2]))));
    x.w = sigf(fmaf(q0, w[3], fmaf(q1, w[7], fmaf(q2, w[11], bb[3]))));
    dst[p] = x;
  }
}

// ---------------- main GRU + tail kernel ----------------
__global__ __launch_bounds__(NT, 2) void gru_kernel(Params pr) {
  __shared__ float embph_s[8], wveh_s[4], bveh_s[4];
  __shared__ float wlane_s[18 * 16], blane_s[16];
  __shared__ float wf_s[32 * 20], bf_s[20];
  __shared__ float wz_s[20 * 20], bz_s[20];
  __shared__ float wo_s[20];
  __shared__ float bo_s;
  __shared__ float wc_s[4 * 20], bc_s[20], embc_s[8];
  __shared__ int rel_s[56], pfl_s[PP];
  __shared__ float press_s[BPB * PP * 17];
  __shared__ float v_s[BPB * PP * 21];

  const int tid = threadIdx.x;
  const int bl   = tid >> 5;
  const int p    = (tid >> 2) & 7;
  const int s    = (tid >> 1) & 1;
  const int cbit = tid & 1;
  const bool c0  = (cbit == 0);
  const int tq   = tid & 3;

  // stage 0: tail weights -> smem
  if (tid < 8) embph_s[tid] = pr.emb_phase[tid];
  if (tid < 4) { wveh_s[tid] = pr.w_veh[tid]; bveh_s[tid] = pr.b_veh[tid]; }
  for (int i = tid; i < 288; i += NT) wlane_s[i] = pr.w_lane[i];
  if (tid < 16) blane_s[tid] = pr.b_lane[tid];
  for (int i = tid; i < 640; i += NT) wf_s[i] = pr.wf[i];
  if (tid < 20) bf_s[tid] = pr.bf[tid];
  for (int i = tid; i < 400; i += NT) wz_s[i] = pr.wz[i];
  if (tid < 20) bz_s[tid] = pr.bz[tid];
  if (tid < 20) wo_s[tid] = pr.wo[tid];
  if (tid == 0) bo_s = pr.bo[0];
  for (int i = tid; i < 80; i += NT) wc_s[i] = pr.wc[i];
  if (tid < 20) bc_s[tid] = pr.bc[tid];
  if (tid < 8) embc_s[tid] = pr.emb_const[tid];
  if (tid < 56) rel_s[tid] = pr.relation[tid];
  if (tid < PP) pfl_s[tid] = pr.pfl[tid];
  __syncthreads();

  const long b = (long)blockIdx.x * BPB + bl;
  const bool active = (b < (long)pr.B);
  const long bcl = active ? b : (long)(pr.B - 1);

  // loop-resident weights (56 ull = 112 regs)
  ull w[7][8];
  {
    const ulonglong2* wp = reinterpret_cast<const ulonglong2*>(&g_wbuf[s][cbit][0][0]);
#pragma unroll
    for (int kk = 0; kk < 7; kk++) {
      ulonglong2 a0 = wp[kk * 4 + 0], a1 = wp[kk * 4 + 1];
      ulonglong2 a2 = wp[kk * 4 + 2], a3 = wp[kk * 4 + 3];
      w[kk][0] = a0.x; w[kk][1] = a0.y; w[kk][2] = a1.x; w[kk][3] = a1.y;
      w[kk][4] = a2.x; w[kk][5] = a2.y; w[kk][6] = a3.x; w[kk][7] = a3.y;
    }
  }
  ull bias[11];
  if (c0) {
    const ull* bp = reinterpret_cast<const ull*>(&g_bias[s][0]);
#pragma unroll
    for (int i = 0; i < 11; i++) bias[i] = bp[i];
  } else {
#pragma unroll
    for (int i = 0; i < 11; i++) bias[i] = 0ull;
  }

  float h[5], ho[5];
#pragma unroll
  for (int j = 0; j < 5; j++) { h[j] = 0.f; ho[j] = 0.f; }

  const float4* xp = &g_xbuf[bcl * TT * PP + p];
  float4 xq = xp[0];

  for (int t = 0; t < TT; t++) {
    float4 xn = make_float4(0.f, 0.f, 0.f, 0.f);
    if (t + 1 < TT) xn = xp[(t + 1) * PP];

    float vals[7];
    vals[0] = c0 ? xq.x : h[3];
    vals[1] = c0 ? xq.y : h[4];
    vals[2] = c0 ? xq.z : ho[0];
    vals[3] = c0 ? xq.w : ho[1];
    vals[4] = c0 ? h[0] : ho[2];
    vals[5] = c0 ? h[1] : ho[3];
    vals[6] = c0 ? h[2] : ho[4];

    ull A[11];
    {
      ull s2 = pk2(vals[0]);
#pragma unroll
      for (int i = 0; i < 5; i++) A[i] = f2fma(s2, w[0][i], bias[i]);
#pragma unroll
      for (int i = 0; i < 3; i++) A[5 + i] = f2fma(s2, w[0][5 + i], bias[5 + i]);
      A[8] = bias[8]; A[9] = bias[9]; A[10] = bias[10];
    }
#pragma unroll
    for (int kk = 1; kk < 7; kk++) {
      ull s2 = pk2(vals[kk]);
#pragma unroll
      for (int i = 0; i < 5; i++) A[i] = f2fma(s2, w[kk][i], A[i]);
      const int nb = (kk < 4) ? 5 : 8;   // P bucket (kk<4) vs Q bucket
#pragma unroll
      for (int i = 0; i < 3; i++) A[nb + i] = f2fma(s2, w[kk][5 + i], A[nb + i]);
    }

    // combine partial sums across c (xor 1)
    ull Ao[11];
#pragma unroll
    for (int i = 0; i < 11; i++) Ao[i] = __shfl_xor_sync(0xffffffffu, A[i], 1);
#pragma unroll
    for (int i = 0; i < 5; i++) A[i] = add2(A[i], Ao[i]);

    float a[10];
#pragma unroll
    for (int i = 0; i < 5; i++) upk(A[i], a[2 * i], a[2 * i + 1]);
    float gnf[6], hnf[6];
#pragma unroll
    for (int i = 0; i < 3; i++) {
      ull gn = c0 ? A[5 + i] : Ao[5 + i];              // x-side n pre-act (+bih_n)
      ull hx = c0 ? Ao[5 + i] : A[5 + i];              // partner's h-side P partial
      ull hn = add2(add2(hx, A[8 + i]), Ao[8 + i]);    // full h-side n pre-act (+bhh_n)
      upk(gn, gnf[2 * i], gnf[2 * i + 1]);
      upk(hn, hnf[2 * i], hnf[2 * i + 1]);
    }

#pragma unroll
    for (int j = 0; j < 5; j++) {
      float r = sigf(a[j]);
      float z = sigf(a[5 + j]);
      float n = tanh_ap(fmaf(r, hnf[j], gnf[j]));
      h[j] = fmaf(z, h[j] - n, n);
    }
#pragma unroll
    for (int j = 0; j < 5; j++) ho[j] = __shfl_xor_sync(0xffffffffu, h[j], 2);
    xq = xn;
  }

  // ---- tail: lane projection -> pressure -> pair network ----
  {
    float ha[10];
#pragma unroll
    for (int j = 0; j < 5; j++) {
      ha[j]     = (s == 0) ? h[j]  : ho[j];
      ha[5 + j] = (s == 0) ? ho[j] : h[j];
    }
    float lf[18];
    float veh = pr.feat[bcl * 16 + 8 + p];
    int pidx = (int)pr.feat[bcl * 16 + p];
#pragma unroll
    for (int j = 0; j < 4; j++) lf[j] = sigf(fmaf(veh, wveh_s[j], bveh_s[j]));
#pragma unroll
    for (int j = 0; j < 4; j++) lf[4 + j] = sigf(embph_s[pidx * 4 + j]);
#pragma unroll
    for (int i = 0; i < 10; i++) lf[8 + i] = ha[i];

    const int lrow = bl * 8 + p;
#pragma unroll
    for (int mm = 0; mm < 4; mm++) {
      int m = 4 * tq + mm;
      float acc = blane_s[m];
#pragma unroll
      for (int k = 0; k < 18; k++) acc = fmaf(lf[k], wlane_s[k * 16 + m], acc);
      press_s[lrow * 17 + m] = 2.0f * fmaxf(acc, 0.f);
    }
    __syncwarp();
    float pf[16];
#pragma unroll
    for (int k = 0; k < 16; k++) pf[k] = press_s[lrow * 17 + k];
#pragma unroll
    for (int mm = 0; mm < 5; mm++) {
      int m = 5 * tq + mm;
      float acc = 0.f;
#pragma unroll
      for (int k = 0; k < 16; k++) acc = fmaf(pf[k], wf_s[(16 + k) * 20 + m], acc);
      v_s[lrow * 21 + m] = acc;
    }
    __syncwarp();
  }
  {
    const int iph = p;
    const int li = pfl_s[iph];
    const float* pi = &press_s[(bl * 8 + li) * 17];

    float u[20];
#pragma unroll
    for (int m = 0; m < 20; m++) u[m] = bf_s[m];
#pragma unroll
    for (int k = 0; k < 16; k++) {
      float sv = pi[k];
#pragma unroll
      for (int m = 0; m < 20; m++) u[m] = fmaf(sv, wf_s[k * 20 + m], u[m]);
    }

    float acc = 0.f;
    const int jpS = tq * 2;
    const int jpN = (tq == 3) ? 1 : 2;
    for (int q = 0; q < jpN; q++) {
      int jp = jpS + q;
      int j = jp + (jp >= iph ? 1 : 0);
      int lj = pfl_s[j];
      const float* vj = &v_s[(bl * 8 + lj) * 21];
      int rel = rel_s[iph * 7 + jp];
      const float* e = &embc_s[rel * 4];
      float ttv[20];
#pragma unroll
      for (int m = 0; m < 20; m++) {
        float y = bc_s[m];
#pragma unroll
        for (int c = 0; c < 4; c++) y = fmaf(e[c], wc_s[c * 20 + m], y);
        y = fmaxf(y, 0.f);
        ttv[m] = fmaxf(u[m] + vj[m], 0.f) * y;
      }
      float z2[20];
#pragma unroll
      for (int m = 0; m < 20; m++) z2[m] = bz_s[m];
#pragma unroll
      for (int m = 0; m < 20; m++) {
        float sv = ttv[m];
#pragma unroll
        for (int m2 = 0; m2 < 20; m2++) z2[m2] = fmaf(sv, wz_s[m * 20 + m2], z2[m2]);
      }
      float zs = bo_s;
#pragma unroll
      for (int m2 = 0; m2 < 20; m2++) zs = fmaf(fmaxf(z2[m2], 0.f), wo_s[m2], zs);
      acc += zs;
    }
    acc += __shfl_xor_sync(0xffffffffu, acc, 1);
    acc += __shfl_xor_sync(0xffffffffu, acc, 2);
    if (tq == 0 && active) pr.out[b * PP + iph] = acc;
  }
}

extern "C" void kernel_launch(void* const* d_in, const int* in_sizes, int n_in,
                              void* d_out, int out_size) {
  Params pr;
  pr.feat      = (const float*)d_in[0];
  pr.hist      = (const float*)d_in[1];
  pr.relation  = (const int*)  d_in[2];
  pr.pfl       = (const int*)  d_in[3];
  pr.emb_phase = (const float*)d_in[4];
  pr.w_veh     = (const float*)d_in[5];
  pr.b_veh     = (const float*)d_in[6];
  pr.w_hist    = (const float*)d_in[7];
  pr.b_hist    = (const float*)d_in[8];
  pr.gwih      = (const float*)d_in[9];
  pr.gwhh      = (const float*)d_in[10];
  pr.gbih      = (const float*)d_in[11];
  pr.gbhh      = (const float*)d_in[12];
  pr.w_lane    = (const float*)d_in[13];
  pr.b_lane    = (const float*)d_in[14];
  pr.emb_const = (const float*)d_in[15];
  pr.wf        = (const float*)d_in[16];
  pr.bf        = (const float*)d_in[17];
  pr.wc        = (const float*)d_in[18];
  pr.bc        = (const float*)d_in[19];
  pr.wz        = (const float*)d_in[20];
  pr.bz        = (const float*)d_in[21];
  pr.wo        = (const float*)d_in[22];
  pr.bo        = (const float*)d_in[23];
  pr.out       = (float*)d_out;
  pr.B         = in_sizes[0] / (2 * PP);

  prep_weights<<<1, 128>>>(pr.gwih, pr.gwhh, pr.gbih, pr.gbhh);
  long bt = (long)pr.B * TT;
  precomp_x<<<(int)((bt + 255) / 256), 256>>>(pr.hist, pr.w_hist, pr.b_hist, pr.B);
  int grid = (pr.B + BPB - 1) / BPB;
  gru_kernel<<<grid, NT>>>(pr);
}

// round 5
// speedup vs baseline: 3.0498x; 1.0448x over previous
#include <cuda_runtime.h>

#define PP 8
#define TT 128
#define BPB 2
#define NT 64
#define MAXB 8192

typedef unsigned long long ull;

struct Params {
  const float* feat; const float* hist; const int* relation; const int* pfl;
  const float* emb_phase; const float* w_veh; const float* b_veh;
  const float* w_hist; const float* b_hist;
  const float* gwih; const float* gwhh; const float* gbih; const float* gbhh;
  const float* w_lane; const float* b_lane; const float* emb_const;
  const float* wf; const float* bf; const float* wc; const float* bc;
  const float* wz; const float* bz; const float* wo; const float* bo;
  float* out; int B;
};

// scratch (static device memory — no allocations)
__device__ __align__(16) float4 g_xbuf[(size_t)MAXB * TT * PP];

__device__ __forceinline__ ull pk2(float v) {
  ull d; asm("mov.b64 %0, {%1, %1};" : "=l"(d) : "f"(v)); return d;
}
__device__ __forceinline__ ull pk2b(float lo, float hi) {
  ull d; asm("mov.b64 %0, {%1, %2};" : "=l"(d) : "f"(lo), "f"(hi)); return d;
}
__device__ __forceinline__ ull f2fma(ull a, ull b, ull c) {
  ull d; asm("fma.rn.f32x2 %0, %1, %2, %3;" : "=l"(d) : "l"(a), "l"(b), "l"(c)); return d;
}
__device__ __forceinline__ ull add2(ull a, ull b) {
  ull d; asm("add.rn.f32x2 %0, %1, %2;" : "=l"(d) : "l"(a), "l"(b)); return d;
}
__device__ __forceinline__ void upk(ull v, float& lo, float& hi) {
  asm("mov.b64 {%0, %1}, %2;" : "=f"(lo), "=f"(hi) : "l"(v));
}
__device__ __forceinline__ float tanh_ap(float x) {
  float y; asm("tanh.approx.f32 %0, %1;" : "=f"(y) : "f"(x)); return y;
}
__device__ __forceinline__ float sigf(float v) {
  return fmaf(tanh_ap(0.5f * v), 0.5f, 0.5f);
}

// ---------------- precompute x = sigmoid(hist @ w_hist + b_hist) ----------------
__global__ __launch_bounds__(256) void precomp_x(const float* __restrict__ hist,
                                                 const float* __restrict__ w_hist,
                                                 const float* __restrict__ b_hist, int B) {
  long idx = (long)blockIdx.x * blockDim.x + threadIdx.x;   // over B*T
  if (idx >= (long)B * TT) return;
  const float4* row4 = reinterpret_cast<const float4*>(hist + idx * 24);
  float q[24];
  float4 rr;
#pragma unroll
  for (int i = 0; i < 6; i++) {
    rr = row4[i];
    q[4 * i] = rr.x; q[4 * i + 1] = rr.y; q[4 * i + 2] = rr.z; q[4 * i + 3] = rr.w;
  }
  float w[12], bb[4];
#pragma unroll
  for (int i = 0; i < 12; i++) w[i] = w_hist[i];
#pragma unroll
  for (int j = 0; j < 4; j++) bb[j] = b_hist[j];
  float4* dst = &g_xbuf[idx * PP];
#pragma unroll
  for (int p = 0; p < PP; p++) {
    float q0 = q[p], q1 = q[8 + p], q2 = q[16 + p];
    float4 x;
    x.x = sigf(fmaf(q0, w[0], fmaf(q1, w[4], fmaf(q2, w[8],  bb[0]))));
    x.y = sigf(fmaf(q0, w[1], fmaf(q1, w[5], fmaf(q2, w[9],  bb[1]))));
    x.z = sigf(fmaf(q0, w[2], fmaf(q1, w[6], fmaf(q2, w[10], bb[2]))));
    x.w = sigf(fmaf(q0, w[3], fmaf(q1, w[7], fmaf(q2, w[11], bb[3]))));
    dst[p] = x;
  }
}

// ---------------- main GRU + tail kernel ----------------
__global__ __launch_bounds__(NT, 5) void gru_kernel(Params pr) {
  __shared__ float embph_s[8], wveh_s[4], bveh_s[4];
  __shared__ float wlane_s[18 * 16], blane_s[16];
  __shared__ float wf_s[32 * 20], bf_s[20];
  __shared__ float wz_s[20 * 20], bz_s[20];
  __shared__ float wo_s[20];
  __shared__ float bo_s;
  __shared__ float wc_s[4 * 20], bc_s[20], embc_s[8];
  __shared__ int rel_s[56], pfl_s[PP];
  __shared__ float press_s[BPB * PP * 17];
  __shared__ float v_s[BPB * PP * 21];

  const int tid = threadIdx.x;
  const int bl   = tid >> 5;
  const int p    = (tid >> 2) & 7;
  const int s    = (tid >> 1) & 1;
  const int cbit = tid & 1;
  const bool c0  = (cbit == 0);
  const int tq   = tid & 3;

  // stage 0: tail weights -> smem
  if (tid < 8) embph_s[tid] = pr.emb_phase[tid];
  if (tid < 4) { wveh_s[tid] = pr.w_veh[tid]; bveh_s[tid] = pr.b_veh[tid]; }
  for (int i = tid; i < 288; i += NT) wlane_s[i] = pr.w_lane[i];
  if (tid < 16) blane_s[tid] = pr.b_lane[tid];
  for (int i = tid; i < 640; i += NT) wf_s[i] = pr.wf[i];
  if (tid < 20) bf_s[tid] = pr.bf[tid];
  for (int i = tid; i < 400; i += NT) wz_s[i] = pr.wz[i];
  if (tid < 20) bz_s[tid] = pr.bz[tid];
  if (tid < 20) wo_s[tid] = pr.wo[tid];
  if (tid == 0) bo_s = pr.bo[0];
  for (int i = tid; i < 80; i += NT) wc_s[i] = pr.wc[i];
  if (tid < 20) bc_s[tid] = pr.bc[tid];
  if (tid < 8) embc_s[tid] = pr.emb_const[tid];
  if (tid < 56) rel_s[tid] = pr.relation[tid];
  if (tid < PP) pfl_s[tid] = pr.pfl[tid];

  const long b = (long)blockIdx.x * BPB + bl;
  const bool active = (b < (long)pr.B);
  const long bcl = active ? b : (long)(pr.B - 1);

  // ---- in-kernel weight gather: 56 loop-resident ull regs per thread ----
  const float* gwih = pr.gwih;
  const float* gwhh = pr.gwhh;
  auto wat = [&](int kk, int pos) -> float {
    if (pos >= 15) return 0.f;
    int g = pos / 5, j = pos % 5;
    int grow = g * 10 + 5 * s + j;      // gate rows: r 0..9, z 10..19, n 20..29
    if (c0) {
      if (kk < 4) return gwih[grow * 4 + kk];
      return gwhh[grow * 10 + 5 * s + (kk - 4)];
    } else {
      int hcol = (kk < 2) ? (5 * s + 3 + kk) : (5 * (1 - s) + (kk - 2));
      return gwhh[grow * 10 + hcol];
    }
  };
  ull w[7][8];
#pragma unroll
  for (int kk = 0; kk < 7; kk++)
#pragma unroll
    for (int i = 0; i < 8; i++)
      w[kk][i] = pk2b(wat(kk, 2 * i), wat(kk, 2 * i + 1));

  auto bat = [&](int pos) -> float {
    if (!c0) return 0.f;
    if (pos < 10) { int g = pos / 5, j = pos % 5; int grow = g * 10 + 5 * s + j;
                    return pr.gbih[grow] + pr.gbhh[grow]; }
    if (pos >= 10 && pos < 15) return pr.gbih[20 + 5 * s + (pos - 10)];  // aN bias
    if (pos >= 16 && pos < 21) return pr.gbhh[20 + 5 * s + (pos - 16)];  // aH bias
    return 0.f;
  };
  ull bias[11];
#pragma unroll
  for (int i = 0; i < 11; i++) bias[i] = pk2b(bat(2 * i), bat(2 * i + 1));

  __syncthreads();

  float h[5], ho[5];
#pragma unroll
  for (int j = 0; j < 5; j++) { h[j] = 0.f; ho[j] = 0.f; }

  const float4* xp = &g_xbuf[bcl * TT * PP + p];
  float4 xq = xp[0];

  for (int t = 0; t < TT; t++) {
    float4 xn = make_float4(0.f, 0.f, 0.f, 0.f);
    if (t + 1 < TT) xn = xp[(t + 1) * PP];

    float vals[7];
    vals[0] = c0 ? xq.x : h[3];
    vals[1] = c0 ? xq.y : h[4];
    vals[2] = c0 ? xq.z : ho[0];
    vals[3] = c0 ? xq.w : ho[1];
    vals[4] = c0 ? h[0] : ho[2];
    vals[5] = c0 ? h[1] : ho[3];
    vals[6] = c0 ? h[2] : ho[4];

    ull A[11];
    {
      ull s2 = pk2(vals[0]);
#pragma unroll
      for (int i = 0; i < 5; i++) A[i] = f2fma(s2, w[0][i], bias[i]);
#pragma unroll
      for (int i = 0; i < 3; i++) A[5 + i] = f2fma(s2, w[0][5 + i], bias[5 + i]);
      A[8] = bias[8]; A[9] = bias[9]; A[10] = bias[10];
    }
#pragma unroll
    for (int kk = 1; kk < 7; kk++) {
      ull s2 = pk2(vals[kk]);
#pragma unroll
      for (int i = 0; i < 5; i++) A[i] = f2fma(s2, w[kk][i], A[i]);
      const int nb = (kk < 4) ? 5 : 8;   // P bucket (kk<4) vs Q bucket
#pragma unroll
      for (int i = 0; i < 3; i++) A[nb + i] = f2fma(s2, w[kk][5 + i], A[nb + i]);
    }

    // combine partial sums across c (xor 1)
    ull Ao[11];
#pragma unroll
    for (int i = 0; i < 11; i++) Ao[i] = __shfl_xor_sync(0xffffffffu, A[i], 1);
#pragma unroll
    for (int i = 0; i < 5; i++) A[i] = add2(A[i], Ao[i]);

    float a[10];
#pragma unroll
    for (int i = 0; i < 5; i++) upk(A[i], a[2 * i], a[2 * i + 1]);
    float gnf[6], hnf[6];
#pragma unroll
    for (int i = 0; i < 3; i++) {
      ull gn = c0 ? A[5 + i] : Ao[5 + i];              // x-side n pre-act (+bih_n)
      ull hx = c0 ? Ao[5 + i] : A[5 + i];              // partner's h-side P partial
      ull hn = add2(add2(hx, A[8 + i]), Ao[8 + i]);    // full h-side n pre-act (+bhh_n)
      upk(gn, gnf[2 * i], gnf[2 * i + 1]);
      upk(hn, hnf[2 * i], hnf[2 * i + 1]);
    }

#pragma unroll
    for (int j = 0; j < 5; j++) {
      float r = sigf(a[j]);
      float z = sigf(a[5 + j]);
      float n = tanh_ap(fmaf(r, hnf[j], gnf[j]));
      h[j] = fmaf(z, h[j] - n, n);
    }
#pragma unroll
    for (int j = 0; j < 5; j++) ho[j] = __shfl_xor_sync(0xffffffffu, h[j], 2);
    xq = xn;
  }

  // ---- tail: lane projection -> pressure -> pair network ----
  {
    float ha[10];
#pragma unroll
    for (int j = 0; j < 5; j++) {
      ha[j]     = (s == 0) ? h[j]  : ho[j];
      ha[5 + j] = (s == 0) ? ho[j] : h[j];
    }
    float lf[18];
    float veh = pr.feat[bcl * 16 + 8 + p];
    int pidx = (int)pr.feat[bcl * 16 + p];
#pragma unroll
    for (int j = 0; j < 4; j++) lf[j] = sigf(fmaf(veh, wveh_s[j], bveh_s[j]));
#pragma unroll
    for (int j = 0; j < 4; j++) lf[4 + j] = sigf(embph_s[pidx * 4 + j]);
#pragma unroll
    for (int i = 0; i < 10; i++) lf[8 + i] = ha[i];

    const int lrow = bl * 8 + p;
#pragma unroll
    for (int mm = 0; mm < 4; mm++) {
      int m = 4 * tq + mm;
      float acc = blane_s[m];
#pragma unroll
      for (int k = 0; k < 18; k++) acc = fmaf(lf[k], wlane_s[k * 16 + m], acc);
      press_s[lrow * 17 + m] = 2.0f * fmaxf(acc, 0.f);
    }
    __syncwarp();
    float pf[16];
#pragma unroll
    for (int k = 0; k < 16; k++) pf[k] = press_s[lrow * 17 + k];
#pragma unroll
    for (int mm = 0; mm < 5; mm++) {
      int m = 5 * tq + mm;
      float acc = 0.f;
#pragma unroll
      for (int k = 0; k < 16; k++) acc = fmaf(pf[k], wf_s[(16 + k) * 20 + m], acc);
      v_s[lrow * 21 + m] = acc;
    }
    __syncwarp();
  }
  {
    const int iph = p;
    const int li = pfl_s[iph];
    const float* pi = &press_s[(bl * 8 + li) * 17];

    float u[20];
#pragma unroll
    for (int m = 0; m < 20; m++) u[m] = bf_s[m];
#pragma unroll
    for (int k = 0; k < 16; k++) {
      float sv = pi[k];
#pragma unroll
      for (int m = 0; m < 20; m++) u[m] = fmaf(sv, wf_s[k * 20 + m], u[m]);
    }

    float acc = 0.f;
    const int jpS = tq * 2;
    const int jpN = (tq == 3) ? 1 : 2;
    for (int q = 0; q < jpN; q++) {
      int jp = jpS + q;
      int j = jp + (jp >= iph ? 1 : 0);
      int lj = pfl_s[j];
      const float* vj = &v_s[(bl * 8 + lj) * 21];
      int rel = rel_s[iph * 7 + jp];
      const float* e = &embc_s[rel * 4];
      float ttv[20];
#pragma unroll
      for (int m = 0; m < 20; m++) {
        float y = bc_s[m];
#pragma unroll
        for (int c = 0; c < 4; c++) y = fmaf(e[c], wc_s[c * 20 + m], y);
        y = fmaxf(y, 0.f);
        ttv[m] = fmaxf(u[m] + vj[m], 0.f) * y;
      }
      float z2[20];
#pragma unroll
      for (int m = 0; m < 20; m++) z2[m] = bz_s[m];
#pragma unroll
      for (int m = 0; m < 20; m++) {
        float sv = ttv[m];
#pragma unroll
        for (int m2 = 0; m2 < 20; m2++) z2[m2] = fmaf(sv, wz_s[m * 20 + m2], z2[m2]);
      }
      float zs = bo_s;
#pragma unroll
      for (int m2 = 0; m2 < 20; m2++) zs = fmaf(fmaxf(z2[m2], 0.f), wo_s[m2], zs);
      acc += zs;
    }
    acc += __shfl_xor_sync(0xffffffffu, acc, 1);
    acc += __shfl_xor_sync(0xffffffffu, acc, 2);
    if (tq == 0 && active) pr.out[b * PP + iph] = acc;
  }
}

extern "C" void kernel_launch(void* const* d_in, const int* in_sizes, int n_in,
                              void* d_out, int out_size) {
  Params pr;
  pr.feat      = (const float*)d_in[0];
  pr.hist      = (const float*)d_in[1];
  pr.relation  = (const int*)  d_in[2];
  pr.pfl       = (const int*)  d_in[3];
  pr.emb_phase = (const float*)d_in[4];
  pr.w_veh     = (const float*)d_in[5];
  pr.b_veh     = (const float*)d_in[6];
  pr.w_hist    = (const float*)d_in[7];
  pr.b_hist    = (const float*)d_in[8];
  pr.gwih      = (const float*)d_in[9];
  pr.gwhh      = (const float*)d_in[10];
  pr.gbih      = (const float*)d_in[11];
  pr.gbhh      = (const float*)d_in[12];
  pr.w_lane    = (const float*)d_in[13];
  pr.b_lane    = (const float*)d_in[14];
  pr.emb_const = (const float*)d_in[15];
  pr.wf        = (const float*)d_in[16];
  pr.bf        = (const float*)d_in[17];
  pr.wc        = (const float*)d_in[18];
  pr.bc        = (const float*)d_in[19];
  pr.wz        = (const float*)d_in[20];
  pr.bz        = (const float*)d_in[21];
  pr.wo        = (const float*)d_in[22];
  pr.bo        = (const float*)d_in[23];
  pr.out       = (float*)d_out;
  pr.B         = in_sizes[0] / (2 * PP);

  long bt = (long)pr.B * TT;
  precomp_x<<<(int)((bt + 255) / 256), 256>>>(pr.hist, pr.w_hist, pr.b_hist, pr.B);
  int grid = (pr.B + BPB - 1) / BPB;
  gru_kernel<<<grid, NT>>>(pr);
}

// round 7
// speedup vs baseline: 3.9079x; 1.2814x over previous
#include <cuda_runtime.h>

#define PP 8
#define TT 128
#define BPB 2
#define NT 64
#define MAXB 8192

typedef unsigned long long ull;

struct Params {
  const float* feat; const float* hist; const int* relation; const int* pfl;
  const float* emb_phase; const float* w_veh; const float* b_veh;
  const float* w_hist; const float* b_hist;
  const float* gwih; const float* gwhh; const float* gbih; const float* gbhh;
  const float* w_lane; const float* b_lane; const float* emb_const;
  const float* wf; const float* bf; const float* wc; const float* bc;
  const float* wz; const float* bz; const float* wo; const float* bo;
  float* out; int B;
};

// scratch (static device memory — no allocations)
__device__ __align__(16) float4 g_xbuf[(size_t)MAXB * TT * PP];

__device__ __forceinline__ ull pk2(float v) {
  ull d; asm("mov.b64 %0, {%1, %1};" : "=l"(d) : "f"(v)); return d;
}
__device__ __forceinline__ ull pk2b(float lo, float hi) {
  ull d; asm("mov.b64 %0, {%1, %2};" : "=l"(d) : "f"(lo), "f"(hi)); return d;
}
__device__ __forceinline__ ull f2fma(ull a, ull b, ull c) {
  ull d; asm("fma.rn.f32x2 %0, %1, %2, %3;" : "=l"(d) : "l"(a), "l"(b), "l"(c)); return d;
}
__device__ __forceinline__ ull add2(ull a, ull b) {
  ull d; asm("add.rn.f32x2 %0, %1, %2;" : "=l"(d) : "l"(a), "l"(b)); return d;
}
__device__ __forceinline__ void upk(ull v, float& lo, float& hi) {
  asm("mov.b64 {%0, %1}, %2;" : "=f"(lo), "=f"(hi) : "l"(v));
}
__device__ __forceinline__ float loF(ull v) { float a, b; upk(v, a, b); return a; }
__device__ __forceinline__ float hiF(ull v) { float a, b; upk(v, a, b); return b; }
__device__ __forceinline__ float tanh_ap(float x) {
  float y; asm("tanh.approx.f32 %0, %1;" : "=f"(y) : "f"(x)); return y;
}
__device__ __forceinline__ float sigf(float v) {
  return fmaf(tanh_ap(0.5f * v), 0.5f, 0.5f);
}

// ---------------- precompute x = sigmoid(hist @ w_hist + b_hist) ----------------
__global__ __launch_bounds__(256) void precomp_x(const float* __restrict__ hist,
                                                 const float* __restrict__ w_hist,
                                                 const float* __restrict__ b_hist, int B) {
  long idx = (long)blockIdx.x * blockDim.x + threadIdx.x;   // over B*T
  if (idx >= (long)B * TT) return;
  const float4* row4 = reinterpret_cast<const float4*>(hist + idx * 24);
  float q[24];
  float4 rr;
#pragma unroll
  for (int i = 0; i < 6; i++) {
    rr = row4[i];
    q[4 * i] = rr.x; q[4 * i + 1] = rr.y; q[4 * i + 2] = rr.z; q[4 * i + 3] = rr.w;
  }
  float w[12], bb[4];
#pragma unroll
  for (int i = 0; i < 12; i++) w[i] = w_hist[i];
#pragma unroll
  for (int j = 0; j < 4; j++) bb[j] = b_hist[j];
  float4* dst = &g_xbuf[idx * PP];
#pragma unroll
  for (int p = 0; p < PP; p++) {
    float q0 = q[p], q1 = q[8 + p], q2 = q[16 + p];
    float4 x;
    x.x = sigf(fmaf(q0, w[0], fmaf(q1, w[4], fmaf(q2, w[8],  bb[0]))));
    x.y = sigf(fmaf(q0, w[1], fmaf(q1, w[5], fmaf(q2, w[9],  bb[1]))));
    x.z = sigf(fmaf(q0, w[2], fmaf(q1, w[6], fmaf(q2, w[10], bb[2]))));
    x.w = sigf(fmaf(q0, w[3], fmaf(q1, w[7], fmaf(q2, w[11], bb[3]))));
    dst[p] = x;
  }
}

// ---------------- main GRU + tail kernel ----------------
// Slot packing per thread (16 lanes as 8 f32x2 regs):
//   A[0..4] = (r_j, z_j) pairs, j=0..4 of this s-half
//   A[5..7] = n-gate P bucket: {n0,n1},{n2,n3},{n4,-}
//   A[8..10]= n-gate Q bucket: same shape
// c0 inputs: x0..x3 (P), h0,h1,h2 (Q).  c1 inputs: h3,h4,ho0,ho1 (P), ho2..ho4 (Q).
// Ownership: c0 computes h0,h1,h2; c1 computes h3,h4.
__global__ __launch_bounds__(NT, 6) void gru_kernel(Params pr) {
  __shared__ float embph_s[8], wveh_s[4], bveh_s[4];
  __shared__ float wlane_s[18 * 16], blane_s[16];
  __shared__ float wf_s[32 * 20], bf_s[20];
  __shared__ float wz_s[20 * 20], bz_s[20];
  __shared__ float wo_s[20];
  __shared__ float bo_s;
  __shared__ float wc_s[4 * 20], bc_s[20], embc_s[8];
  __shared__ int rel_s[56], pfl_s[PP];
  __shared__ float press_s[BPB * PP * 17];
  __shared__ float v_s[BPB * PP * 21];

  const int tid = threadIdx.x;
  const int bl   = tid >> 5;
  const int p    = (tid >> 2) & 7;
  const int s    = (tid >> 1) & 1;
  const int cbit = tid & 1;
  const bool c0  = (cbit == 0);
  const int tq   = tid & 3;

  // stage 0: tail weights -> smem
  if (tid < 8) embph_s[tid] = pr.emb_phase[tid];
  if (tid < 4) { wveh_s[tid] = pr.w_veh[tid]; bveh_s[tid] = pr.b_veh[tid]; }
  for (int i = tid; i < 288; i += NT) wlane_s[i] = pr.w_lane[i];
  if (tid < 16) blane_s[tid] = pr.b_lane[tid];
  for (int i = tid; i < 640; i += NT) wf_s[i] = pr.wf[i];
  if (tid < 20) bf_s[tid] = pr.bf[tid];
  for (int i = tid; i < 400; i += NT) wz_s[i] = pr.wz[i];
  if (tid < 20) bz_s[tid] = pr.bz[tid];
  if (tid < 20) wo_s[tid] = pr.wo[tid];
  if (tid == 0) bo_s = pr.bo[0];
  for (int i = tid; i < 80; i += NT) wc_s[i] = pr.wc[i];
  if (tid < 20) bc_s[tid] = pr.bc[tid];
  if (tid < 8) embc_s[tid] = pr.emb_const[tid];
  if (tid < 56) rel_s[tid] = pr.relation[tid];
  if (tid < PP) pfl_s[tid] = pr.pfl[tid];

  const long b = (long)blockIdx.x * BPB + bl;
  const bool active = (b < (long)pr.B);
  const long bcl = active ? b : (long)(pr.B - 1);

  // ---- in-kernel weight gather: 56 loop-resident ull regs per thread ----
  const float* gwih = pr.gwih;
  const float* gwhh = pr.gwhh;
  auto wat = [&](int kk, int pos) -> float {
    if (pos >= 15) return 0.f;
    int grow;
    if (pos < 10) { int j = pos >> 1, g = pos & 1; grow = g * 10 + 5 * s + j; }
    else          { grow = 20 + 5 * s + (pos - 10); }
    if (c0) {
      if (kk < 4) return gwih[grow * 4 + kk];
      return gwhh[grow * 10 + 5 * s + (kk - 4)];
    } else {
      int hcol = (kk < 2) ? (5 * s + 3 + kk) : (5 * (1 - s) + (kk - 2));
      return gwhh[grow * 10 + hcol];
    }
  };
  ull w[7][8];
#pragma unroll
  for (int kk = 0; kk < 7; kk++)
#pragma unroll
    for (int i = 0; i < 8; i++)
      w[kk][i] = pk2b(wat(kk, 2 * i), wat(kk, 2 * i + 1));

  auto bat = [&](int pos) -> float {
    if (!c0) return 0.f;
    if (pos < 10) { int j = pos >> 1, g = pos & 1; int grow = g * 10 + 5 * s + j;
                    return pr.gbih[grow] + pr.gbhh[grow]; }
    if (pos >= 10 && pos < 15) return pr.gbih[20 + 5 * s + (pos - 10)];  // P (bih_n)
    if (pos >= 16 && pos < 21) return pr.gbhh[20 + 5 * s + (pos - 16)];  // Q (bhh_n)
    return 0.f;
  };
  ull bias[11];
#pragma unroll
  for (int i = 0; i < 11; i++) bias[i] = pk2b(bat(2 * i), bat(2 * i + 1));

  __syncthreads();

  // owned h (c0: h0,h1,h2 ; c1: h3,h4,[garbage]) and c1's other-half cache
  float hO[3] = {0.f, 0.f, 0.f};
  float hx0 = 0.f, hx1 = 0.f, hx2 = 0.f, hx3 = 0.f, hx4 = 0.f;

  const float4* xp = &g_xbuf[bcl * TT * PP + p];
  float4 xq = xp[0];

  for (int t = 0; t < TT; t++) {
    float4 xn = make_float4(0.f, 0.f, 0.f, 0.f);
    if (t + 1 < TT) xn = xp[(t + 1) * PP];

    float vals[7];
    vals[0] = c0 ? xq.x : hO[0];
    vals[1] = c0 ? xq.y : hO[1];
    vals[2] = c0 ? xq.z : hx0;
    vals[3] = c0 ? xq.w : hx1;
    vals[4] = c0 ? hO[0] : hx2;
    vals[5] = c0 ? hO[1] : hx3;
    vals[6] = c0 ? hO[2] : hx4;

    ull A[11];
    {
      ull s2 = pk2(vals[0]);
#pragma unroll
      for (int i = 0; i < 5; i++) A[i] = f2fma(s2, w[0][i], bias[i]);
#pragma unroll
      for (int i = 0; i < 3; i++) A[5 + i] = f2fma(s2, w[0][5 + i], bias[5 + i]);
      A[8] = bias[8]; A[9] = bias[9]; A[10] = bias[10];
    }
#pragma unroll
    for (int kk = 1; kk < 7; kk++) {
      ull s2 = pk2(vals[kk]);
#pragma unroll
      for (int i = 0; i < 5; i++) A[i] = f2fma(s2, w[kk][i], A[i]);
      const int nb = (kk < 4) ? 5 : 8;
#pragma unroll
      for (int i = 0; i < 3; i++) A[nb + i] = f2fma(s2, w[kk][5 + i], A[nb + i]);
    }

    // c1 pre-sums its full h-side n partial (c0's S unused)
    ull S0 = add2(A[5], A[8]);
    ull S1 = add2(A[6], A[9]);
    ull S2 = add2(A[7], A[10]);

    // asymmetric exchange: 6 ull shfls
    ull r1 = __shfl_xor_sync(0xffffffffu, c0 ? A[3]  : A[0], 1);
    ull r2 = __shfl_xor_sync(0xffffffffu, c0 ? A[4]  : A[1], 1);
    ull r3 = __shfl_xor_sync(0xffffffffu, c0 ? A[6]  : A[2], 1);
    ull r4 = __shfl_xor_sync(0xffffffffu, c0 ? A[7]  : S0,   1);
    ull r5 = __shfl_xor_sync(0xffffffffu, c0 ? A[9]  : S1,   1);
    ull r6 = __shfl_xor_sync(0xffffffffu, c0 ? A[10] : S2,   1);

    // combined RZ for owned slots
    ull rz0 = add2(c0 ? A[0] : A[3], r1);     // c0: j0 ; c1: j3
    ull rz1 = add2(c0 ? A[1] : A[4], r2);     // c0: j1 ; c1: j4
    ull rz2 = add2(A[2], r3);                 // c0: j2 ; c1: garbage
    // c0 hn pairs
    ull hnp0 = add2(r4, A[8]);                // c0: {hn0,hn1}
    ull hnp1 = add2(r5, A[9]);                // c0: {hn2,hn3}

    float gA = c0 ? loF(A[5]) : hiF(r3);
    float hA = c0 ? loF(hnp0) : (hiF(S1) + hiF(r5));
    float gB = c0 ? hiF(A[5]) : loF(r4);
    float hB = c0 ? hiF(hnp0) : (loF(S2) + loF(r6));
    float gC = loF(A[6]);
    float hC = loF(hnp1);

    {
      float rl, zl;
      upk(rz0, rl, zl);
      float rr0 = sigf(rl), zz0 = sigf(zl);
      float nn0 = tanh_ap(fmaf(rr0, hA, gA));
      upk(rz1, rl, zl);
      float rr1 = sigf(rl), zz1 = sigf(zl);
      float nn1 = tanh_ap(fmaf(rr1, hB, gB));
      upk(rz2, rl, zl);
      float rr2 = sigf(rl), zz2 = sigf(zl);
      float nn2 = tanh_ap(fmaf(rr2, hC, gC));
      hO[0] = fmaf(zz0, hO[0] - nn0, nn0);
      hO[1] = fmaf(zz1, hO[1] - nn1, nn1);
      hO[2] = fmaf(zz2, hO[2] - nn2, nn2);   // c1: garbage, never consumed
    }

    // redistribute for next step: only c1 consumes these
    float w3a = __shfl_xor_sync(0xffffffffu, hO[0], 3);
    float w3b = __shfl_xor_sync(0xffffffffu, hO[1], 3);
    float w3c = __shfl_xor_sync(0xffffffffu, hO[2], 3);
    float w2a = __shfl_xor_sync(0xffffffffu, hO[0], 2);
    float w2b = __shfl_xor_sync(0xffffffffu, hO[1], 2);
    hx0 = w3a; hx1 = w3b; hx2 = w3c; hx3 = w2a; hx4 = w2b;

    xq = xn;
  }

  // ---- reassemble full h for tail ----
  float ha[10];
  {
    float t1 = __shfl_xor_sync(0xffffffffu, hO[0], 1);  // c0<-h3 ; c1<-h0
    float t2 = __shfl_xor_sync(0xffffffffu, hO[1], 1);  // c0<-h4 ; c1<-h1
    float t3 = __shfl_xor_sync(0xffffffffu, hO[2], 1);  //          c1<-h2
    float hf0 = c0 ? hO[0] : t1;
    float hf1 = c0 ? hO[1] : t2;
    float hf2 = c0 ? hO[2] : t3;
    float hf3 = c0 ? t1 : hO[0];
    float hf4 = c0 ? t2 : hO[1];
    float hg0 = __shfl_xor_sync(0xffffffffu, hf0, 2);
    float hg1 = __shfl_xor_sync(0xffffffffu, hf1, 2);
    float hg2 = __shfl_xor_sync(0xffffffffu, hf2, 2);
    float hg3 = __shfl_xor_sync(0xffffffffu, hf3, 2);
    float hg4 = __shfl_xor_sync(0xffffffffu, hf4, 2);
    float hf[5] = {hf0, hf1, hf2, hf3, hf4};
    float hg[5] = {hg0, hg1, hg2, hg3, hg4};
#pragma unroll
    for (int j = 0; j < 5; j++) {
      ha[j]     = (s == 0) ? hf[j] : hg[j];
      ha[5 + j] = (s == 0) ? hg[j] : hf[j];
    }
  }

  // ---- tail: lane projection -> pressure -> pair network ----
  {
    float lf[18];
    float veh = pr.feat[bcl * 16 + 8 + p];
    int pidx = (int)pr.feat[bcl * 16 + p];
#pragma unroll
    for (int j = 0; j < 4; j++) lf[j] = sigf(fmaf(veh, wveh_s[j], bveh_s[j]));
#pragma unroll
    for (int j = 0; j < 4; j++) lf[4 + j] = sigf(embph_s[pidx * 4 + j]);
#pragma unroll
    for (int i = 0; i < 10; i++) lf[8 + i] = ha[i];

    const int lrow = bl * 8 + p;
#pragma unroll
    for (int mm = 0; mm < 4; mm++) {
      int m = 4 * tq + mm;
      float acc = blane_s[m];
#pragma unroll
      for (int k = 0; k < 18; k++) acc = fmaf(lf[k], wlane_s[k * 16 + m], acc);
      press_s[lrow * 17 + m] = 2.0f * fmaxf(acc, 0.f);
    }
    __syncwarp();
    float pf[16];
#pragma unroll
    for (int k = 0; k < 16; k++) pf[k] = press_s[lrow * 17 + k];
#pragma unroll
    for (int mm = 0; mm < 5; mm++) {
      int m = 5 * tq + mm;
      float acc = 0.f;
#pragma unroll
      for (int k = 0; k < 16; k++) acc = fmaf(pf[k], wf_s[(16 + k) * 20 + m], acc);
      v_s[lrow * 21 + m] = acc;
    }
    __syncwarp();
  }
  {
    const int iph = p;
    const int li = pfl_s[iph];
    const float* pi = &press_s[(bl * 8 + li) * 17];

    float u[20];
#pragma unroll
    for (int m = 0; m < 20; m++) u[m] = bf_s[m];
#pragma unroll
    for (int k = 0; k < 16; k++) {
      float sv = pi[k];
#pragma unroll
      for (int m = 0; m < 20; m++) u[m] = fmaf(sv, wf_s[k * 20 + m], u[m]);
    }

    float acc = 0.f;
    const int jpS = tq * 2;
    const int jpN = (tq == 3) ? 1 : 2;
    for (int q = 0; q < jpN; q++) {
      int jp = jpS + q;
      int j = jp + (jp >= iph ? 1 : 0);
      int lj = pfl_s[j];
      const float* vj = &v_s[(bl * 8 + lj) * 21];
      int rel = rel_s[iph * 7 + jp];
      const float* e = &embc_s[rel * 4];
      float ttv[20];
#pragma unroll
      for (int m = 0; m < 20; m++) {
        float y = bc_s[m];
#pragma unroll
        for (int c = 0; c < 4; c++) y = fmaf(e[c], wc_s[c * 20 + m], y);
        y = fmaxf(y, 0.f);
        ttv[m] = fmaxf(u[m] + vj[m], 0.f) * y;
      }
      float z2[20];
#pragma unroll
      for (int m = 0; m < 20; m++) z2[m] = bz_s[m];
#pragma unroll
      for (int m = 0; m < 20; m++) {
        float sv = ttv[m];
#pragma unroll
        for (int m2 = 0; m2 < 20; m2++) z2[m2] = fmaf(sv, wz_s[m * 20 + m2], z2[m2]);
      }
      float zs = bo_s;
#pragma unroll
      for (int m2 = 0; m2 < 20; m2++) zs = fmaf(fmaxf(z2[m2], 0.f), wo_s[m2], zs);
      acc += zs;
    }
    acc += __shfl_xor_sync(0xffffffffu, acc, 1);
    acc += __shfl_xor_sync(0xffffffffu, acc, 2);
    if (tq == 0 && active) pr.out[b * PP + iph] = acc;
  }
}

extern "C" void kernel_launch(void* const* d_in, const int* in_sizes, int n_in,
                              void* d_out, int out_size) {
  Params pr;
  pr.feat      = (const float*)d_in[0];
  pr.hist      = (const float*)d_in[1];
  pr.relation  = (const int*)  d_in[2];
  pr.pfl       = (const int*)  d_in[3];
  pr.emb_phase = (const float*)d_in[4];
  pr.w_veh     = (const float*)d_in[5];
  pr.b_veh     = (const float*)d_in[6];
  pr.w_hist    = (const float*)d_in[7];
  pr.b_hist    = (const float*)d_in[8];
  pr.gwih      = (const float*)d_in[9];
  pr.gwhh      = (const float*)d_in[10];
  pr.gbih      = (const float*)d_in[11];
  pr.gbhh      = (const float*)d_in[12];
  pr.w_lane    = (const float*)d_in[13];
  pr.b_lane    = (const float*)d_in[14];
  pr.emb_const = (const float*)d_in[15];
  pr.wf        = (const float*)d_in[16];
  pr.bf        = (const float*)d_in[17];
  pr.wc        = (const float*)d_in[18];
  pr.bc        = (const float*)d_in[19];
  pr.wz        = (const float*)d_in[20];
  pr.bz        = (const float*)d_in[21];
  pr.wo        = (const float*)d_in[22];
  pr.bo        = (const float*)d_in[23];
  pr.out       = (float*)d_out;
  pr.B         = in_sizes[0] / (2 * PP);

  long bt = (long)pr.B * TT;
  precomp_x<<<(int)((bt + 255) / 256), 256>>>(pr.hist, pr.w_hist, pr.b_hist, pr.B);
  int grid = (pr.B + BPB - 1) / BPB;
  gru_kernel<<<grid, NT>>>(pr);
}